// round 7
// baseline (speedup 1.0000x reference)
#include <cuda_runtime.h>
#include <cuda_bf16.h>

// Problem constants (fixed shapes from setup_inputs)
#define BB      4
#define NPTS    8192
#define SS      2048
#define CC      64
#define NSAMPLE 32
#define R2      0.04f     // 0.2^2
#define OUTCH   (3 + CC)  // 67

#define WPB       2        // warps per block
#define NQUERIES  (BB * SS)
#define GRID_QG   2960     // ~20 CTAs/SM * 148 SMs (persistent-ish, work-stealing)

// Scratch: transposed features [B,N,C] (8MB), SoA xyz [B,3,N] (384KB)
__device__ float g_featT[(size_t)BB * NPTS * CC];
__device__ float g_xyzT[(size_t)BB * 3 * NPTS];
__device__ unsigned int g_qctr;      // dynamic work-queue cursor

// ---------------------------------------------------------------------------
// Kernel 1: transpose features [B,C,N] -> [B,N,C]; last y-slice repacks xyz
// [B,N,3] -> [B,3,N]. Also resets the work-queue counter (runs before qg
// in stream order every replay -> graph-capturable and deterministic).
// ---------------------------------------------------------------------------
__global__ __launch_bounds__(256) void transpose_kernel(
    const float* __restrict__ feat,
    const float* __restrict__ xyz)
{
    if (blockIdx.x == 0 && blockIdx.y == 0 && blockIdx.z == 0 &&
        threadIdx.x == 0 && threadIdx.y == 0)
        g_qctr = 0u;

    const int n0 = blockIdx.x * 32;
    const int b  = blockIdx.z;

    if (blockIdx.y == CC / 32) {
        const int t = threadIdx.y * 32 + threadIdx.x;
        if (t < 96) {
            const float v = __ldg(xyz + ((size_t)b * NPTS + n0) * 3 + t);
            const int c = t % 3, n = n0 + t / 3;
            g_xyzT[((size_t)b * 3 + c) * NPTS + n] = v;
        }
        return;
    }

    __shared__ float tsm[32][33];
    const int c0 = blockIdx.y * 32;
    const int tx = threadIdx.x, ty = threadIdx.y;

    const float* fb = feat + (size_t)b * CC * NPTS;
#pragma unroll
    for (int i = 0; i < 4; i++)
        tsm[ty + 8 * i][tx] = fb[(size_t)(c0 + ty + 8 * i) * NPTS + (n0 + tx)];
    __syncthreads();
    float* fT = g_featT + (size_t)b * NPTS * CC;
#pragma unroll
    for (int i = 0; i < 4; i++)
        fT[(size_t)(n0 + ty + 8 * i) * CC + (c0 + tx)] = tsm[tx][ty + 8 * i];
}

// ---------------------------------------------------------------------------
// Kernel 2: fused ball query + group, persistent warps with dynamic stealing.
// Each warp pulls query ids from g_qctr until the pool is empty -> near-
// perfect load balance over the highly variable scan lengths.
// ---------------------------------------------------------------------------
__global__ __launch_bounds__(64, 20) void qg_kernel(
    const float* __restrict__ new_xyz,  // [B, S, 3]
    float* __restrict__ out)            // [B, 67, S, 32]
{
    __shared__ int   sidx[WPB][NSAMPLE];
    __shared__ float sxyz[WPB][NSAMPLE][3];
    __shared__ float tile[WPB][NSAMPLE * 33];

    const int warp = threadIdx.x >> 5;
    const int lane = threadIdx.x & 31;
    const int csub = lane >> 3;       // store: channel sub-id (0..3)
    const int k4   = (lane & 7) * 4;  // store: first of 4 samples

    for (;;) {
        // --- grab next query ------------------------------------------------
        unsigned int w;
        if (lane == 0) w = atomicAdd(&g_qctr, 1u);
        w = __shfl_sync(0xffffffffu, w, 0);
        if (w >= NQUERIES) break;

        const int b = w / SS;
        const int s = w % SS;

        const float* qptr = new_xyz + ((size_t)b * SS + s) * 3;
        const float qx = qptr[0], qy = qptr[1], qz = qptr[2];
        // Reference arithmetic EXACTLY (plain rn ops, no contraction):
        const float q2 = __fadd_rn(__fadd_rn(__fmul_rn(qx, qx), __fmul_rn(qy, qy)),
                                   __fmul_rn(qz, qz));

        const float* xT0 = g_xyzT + ((size_t)b * 3 + 0) * NPTS;
        const float* xT1 = g_xyzT + ((size_t)b * 3 + 1) * NPTS;
        const float* xT2 = g_xyzT + ((size_t)b * 3 + 2) * NPTS;

        // --- Ball query: ascending scan, 128 points per chunk ---------------
        int cnt = 0;
        for (int base = 0; base < NPTS; base += 128) {
            float px[4], py[4], pz[4];
#pragma unroll
            for (int r = 0; r < 4; r++) {
                const int j = base + 32 * r + lane;
                px[r] = __ldg(xT0 + j);
                py[r] = __ldg(xT1 + j);
                pz[r] = __ldg(xT2 + j);
            }
#pragma unroll
            for (int r = 0; r < 4; r++) {
                const float p2  = __fadd_rn(__fadd_rn(__fmul_rn(px[r], px[r]),
                                                      __fmul_rn(py[r], py[r])),
                                            __fmul_rn(pz[r], pz[r]));
                const float qpd = __fadd_rn(__fadd_rn(__fmul_rn(qx, px[r]),
                                                      __fmul_rn(qy, py[r])),
                                            __fmul_rn(qz, pz[r]));
                const float d2  = __fadd_rn(__fadd_rn(q2, p2),
                                            __fmul_rn(-2.0f, qpd));
                const bool in = d2 < R2;
                const unsigned m = __ballot_sync(0xffffffffu, in);
                if (in) {
                    const int pos = cnt + __popc(m & ((1u << lane) - 1u));
                    if (pos < NSAMPLE) {
                        sidx[warp][pos]    = base + 32 * r + lane;
                        sxyz[warp][pos][0] = px[r];
                        sxyz[warp][pos][1] = py[r];
                        sxyz[warp][pos][2] = pz[r];
                    }
                }
                cnt += __popc(m);
            }
            if (cnt >= NSAMPLE) break;             // warp-uniform
        }

        // Empty-ball fallback: slot 0 = point 0 (matches reference idx=0)
        if (cnt == 0 && lane == 0) {
            sidx[warp][0]    = 0;
            sxyz[warp][0][0] = __ldg(xT0 + 0);
            sxyz[warp][0][1] = __ldg(xT1 + 0);
            sxyz[warp][0][2] = __ldg(xT2 + 0);
        }
        __syncwarp();

        const int total = (cnt == 0) ? 1 : ((cnt < NSAMPLE) ? cnt : NSAMPLE);
        const int slot  = (lane < total) ? lane : 0;     // pad with first
        const int myidx = sidx[warp][slot];

        // --- grouped_xyz = xyz[idx] - new_xyz (coords captured in scan) -----
        const size_t cs    = (size_t)SS * NSAMPLE;
        const size_t obase = (((size_t)b * OUTCH) * SS + s) * NSAMPLE + lane;
        out[obase + 0 * cs] = sxyz[warp][slot][0] - qx;
        out[obase + 1 * cs] = sxyz[warp][slot][1] - qy;
        out[obase + 2 * cs] = sxyz[warp][slot][2] - qz;

        // --- grouped_features: wavefront-optimal cooperative gather ---------
        const float* fT = g_featT + (size_t)b * NPTS * CC;
        float*       tw = tile[warp];

#pragma unroll
        for (int h = 0; h < 2; h++) {     // two 32-channel halves
            // 32 coalesced 128B half-row loads (1 wavefront each), MLP=8
#pragma unroll
            for (int m0 = 0; m0 < NSAMPLE; m0 += 8) {
                float v[8];
#pragma unroll
                for (int m = 0; m < 8; m++) {
                    const int im = __shfl_sync(0xffffffffu, myidx, m0 + m);
                    v[m] = __ldg(fT + (size_t)im * CC + h * 32 + lane);
                }
#pragma unroll
                for (int m = 0; m < 8; m++)
                    tw[(m0 + m) * 33 + lane] = v[m];
            }
            __syncwarp();
            // 8 STG.128: each instr covers 4 channels x 8 sample-quads.
#pragma unroll
            for (int cc = 0; cc < 8; cc++) {
                const int c = cc * 4 + csub;          // channel within half
                float4 o;
                o.x = tw[(k4 + 0) * 33 + c];
                o.y = tw[(k4 + 1) * 33 + c];
                o.z = tw[(k4 + 2) * 33 + c];
                o.w = tw[(k4 + 3) * 33 + c];
                float* dst = out + (((size_t)b * OUTCH + 3 + h * 32 + c) * SS + s)
                                 * NSAMPLE + k4;
                *(float4*)dst = o;
            }
            __syncwarp();
        }
    }
}

extern "C" void kernel_launch(void* const* d_in, const int* in_sizes, int n_in,
                              void* d_out, int out_size) {
    const float* xyz      = (const float*)d_in[0];   // [4, 8192, 3]
    const float* new_xyz  = (const float*)d_in[1];   // [4, 2048, 3]
    const float* features = (const float*)d_in[2];   // [4, 64, 8192]
    float* out = (float*)d_out;                      // [4, 67, 2048, 32]

    dim3 tb(32, 8);
    dim3 tg(NPTS / 32, CC / 32 + 1, BB);             // (256, 3, 4)
    transpose_kernel<<<tg, tb>>>(features, xyz);

    qg_kernel<<<GRID_QG, 32 * WPB>>>(new_xyz, out);
}

// round 8
// speedup vs baseline: 1.3381x; 1.3381x over previous
#include <cuda_runtime.h>
#include <cuda_bf16.h>

// Problem constants (fixed shapes from setup_inputs)
#define BB      4
#define NPTS    8192
#define SS      2048
#define CC      64
#define NSAMPLE 32
#define R2      0.04f     // 0.2^2
#define OUTCH   (3 + CC)  // 67

#define WPB     2         // warps per block

// Scratch: transposed features [B,N,C] (8MB); xyz+p2 AoS [B,N] float4 (512KB)
__device__ float  g_featT[(size_t)BB * NPTS * CC];
__device__ float4 g_xyzP4[(size_t)BB * NPTS];

// ---------------------------------------------------------------------------
// Kernel 1: transpose features [B,C,N] -> [B,N,C]; last y-slice packs xyz
// into float4 (x, y, z, p2) with p2 computed in the scan's EXACT rounding.
// block (32,8), grid (N/32, C/32 + 1, B).
// ---------------------------------------------------------------------------
__global__ __launch_bounds__(256) void transpose_kernel(
    const float* __restrict__ feat,
    const float* __restrict__ xyz)
{
    const int n0 = blockIdx.x * 32;
    const int b  = blockIdx.z;

    if (blockIdx.y == CC / 32) {
        const int t = threadIdx.y * 32 + threadIdx.x;
        if (t < 32) {
            const int n = n0 + t;
            const float x = __ldg(xyz + ((size_t)b * NPTS + n) * 3 + 0);
            const float y = __ldg(xyz + ((size_t)b * NPTS + n) * 3 + 1);
            const float z = __ldg(xyz + ((size_t)b * NPTS + n) * 3 + 2);
            // p2 bit-identical to the reference's p2 = (x*x + y*y) + z*z
            const float p2 = __fadd_rn(__fadd_rn(__fmul_rn(x, x),
                                                 __fmul_rn(y, y)),
                                       __fmul_rn(z, z));
            g_xyzP4[(size_t)b * NPTS + n] = make_float4(x, y, z, p2);
        }
        return;
    }

    __shared__ float tsm[32][33];
    const int c0 = blockIdx.y * 32;
    const int tx = threadIdx.x, ty = threadIdx.y;

    const float* fb = feat + (size_t)b * CC * NPTS;
#pragma unroll
    for (int i = 0; i < 4; i++)
        tsm[ty + 8 * i][tx] = fb[(size_t)(c0 + ty + 8 * i) * NPTS + (n0 + tx)];
    __syncthreads();
    float* fT = g_featT + (size_t)b * NPTS * CC;
#pragma unroll
    for (int i = 0; i < 4; i++)
        fT[(size_t)(n0 + ty + 8 * i) * CC + (c0 + tx)] = tsm[tx][ty + 8 * i];
}

// ---------------------------------------------------------------------------
// Kernel 2: fused ball query + group. One warp per query, 2 warps/block.
// Scan: float4 (x,y,z,p2) AoS, 128 pts/chunk, software-pipelined prefetch,
// 7 fp-instr predicate (p2 precomputed). Gather: round-6 wavefront-optimal.
// ---------------------------------------------------------------------------
__global__ __launch_bounds__(64) void qg_kernel(
    const float* __restrict__ new_xyz,  // [B, S, 3]
    float* __restrict__ out)            // [B, 67, S, 32]
{
    __shared__ int   sidx[WPB][NSAMPLE];
    __shared__ float sxyz[WPB][NSAMPLE][3];
    __shared__ float tile[WPB][NSAMPLE * 33];

    const int warp = threadIdx.x >> 5;
    const int lane = threadIdx.x & 31;
    const int w    = blockIdx.x * WPB + warp;  // query id in [0, B*S)
    const int b    = w / SS;
    const int s    = w % SS;

    const float* qptr = new_xyz + ((size_t)b * SS + s) * 3;
    const float qx = qptr[0], qy = qptr[1], qz = qptr[2];
    // Reference arithmetic EXACTLY (plain rn ops, no contraction):
    const float q2 = __fadd_rn(__fadd_rn(__fmul_rn(qx, qx), __fmul_rn(qy, qy)),
                               __fmul_rn(qz, qz));

    const float4* xp = g_xyzP4 + (size_t)b * NPTS;

    // --- Ball query: pipelined ascending scan, 128 points per chunk --------
    int cnt = 0;
    float4 cur[4];
#pragma unroll
    for (int r = 0; r < 4; r++) cur[r] = __ldg(xp + 32 * r + lane);

    for (int base = 0; base < NPTS; base += 128) {
        // prefetch next chunk before the break decision (hides load latency)
        float4 nxt[4];
        if (base + 128 < NPTS) {
#pragma unroll
            for (int r = 0; r < 4; r++)
                nxt[r] = __ldg(xp + base + 128 + 32 * r + lane);
        }
#pragma unroll
        for (int r = 0; r < 4; r++) {
            const float4 p = cur[r];
            const float qpd = __fadd_rn(__fadd_rn(__fmul_rn(qx, p.x),
                                                  __fmul_rn(qy, p.y)),
                                        __fmul_rn(qz, p.z));
            const float d2  = __fadd_rn(__fadd_rn(q2, p.w),
                                        __fmul_rn(-2.0f, qpd));
            const bool in = d2 < R2;
            const unsigned m = __ballot_sync(0xffffffffu, in);
            if (in) {
                const int pos = cnt + __popc(m & ((1u << lane) - 1u));
                if (pos < NSAMPLE) {
                    sidx[warp][pos]    = base + 32 * r + lane;
                    sxyz[warp][pos][0] = p.x;
                    sxyz[warp][pos][1] = p.y;
                    sxyz[warp][pos][2] = p.z;
                }
            }
            cnt += __popc(m);
        }
        if (cnt >= NSAMPLE) break;             // warp-uniform
#pragma unroll
        for (int r = 0; r < 4; r++) cur[r] = nxt[r];
    }

    // Empty-ball fallback: slot 0 = point 0 (matches reference idx=0)
    if (cnt == 0 && lane == 0) {
        const float4 p0 = __ldg(xp);
        sidx[warp][0]    = 0;
        sxyz[warp][0][0] = p0.x;
        sxyz[warp][0][1] = p0.y;
        sxyz[warp][0][2] = p0.z;
    }
    __syncwarp();

    const int total = (cnt == 0) ? 1 : ((cnt < NSAMPLE) ? cnt : NSAMPLE);
    const int slot  = (lane < total) ? lane : 0;     // pad with first
    const int myidx = sidx[warp][slot];

    // --- grouped_xyz = xyz[idx] - new_xyz (coords captured during scan) ----
    const size_t cs    = (size_t)SS * NSAMPLE;
    const size_t obase = (((size_t)b * OUTCH) * SS + s) * NSAMPLE + lane;
    out[obase + 0 * cs] = sxyz[warp][slot][0] - qx;
    out[obase + 1 * cs] = sxyz[warp][slot][1] - qy;
    out[obase + 2 * cs] = sxyz[warp][slot][2] - qz;

    // --- grouped_features: wavefront-optimal cooperative gather -------------
    const float* fT = g_featT + (size_t)b * NPTS * CC;
    float*       tw = tile[warp];

    const int csub = lane >> 3;       // store: channel sub-id (0..3)
    const int k4   = (lane & 7) * 4;  // store: first of 4 samples

#pragma unroll
    for (int h = 0; h < 2; h++) {     // two 32-channel halves
        // 32 coalesced 128B half-row loads (1 wavefront each), MLP=8
#pragma unroll
        for (int m0 = 0; m0 < NSAMPLE; m0 += 8) {
            float v[8];
#pragma unroll
            for (int m = 0; m < 8; m++) {
                const int im = __shfl_sync(0xffffffffu, myidx, m0 + m);
                v[m] = __ldg(fT + (size_t)im * CC + h * 32 + lane);
            }
#pragma unroll
            for (int m = 0; m < 8; m++)
                tw[(m0 + m) * 33 + lane] = v[m];
        }
        __syncwarp();
        // 8 STG.128: each instr covers 4 channels x 8 sample-quads.
        // LDS banks: (k4+j)*33 + c == k4+j+c (mod 32) -> conflict-free
#pragma unroll
        for (int cc = 0; cc < 8; cc++) {
            const int c = cc * 4 + csub;          // channel within half
            float4 o;
            o.x = tw[(k4 + 0) * 33 + c];
            o.y = tw[(k4 + 1) * 33 + c];
            o.z = tw[(k4 + 2) * 33 + c];
            o.w = tw[(k4 + 3) * 33 + c];
            float* dst = out + (((size_t)b * OUTCH + 3 + h * 32 + c) * SS + s)
                             * NSAMPLE + k4;
            *(float4*)dst = o;
        }
        __syncwarp();
    }
}

extern "C" void kernel_launch(void* const* d_in, const int* in_sizes, int n_in,
                              void* d_out, int out_size) {
    const float* xyz      = (const float*)d_in[0];   // [4, 8192, 3]
    const float* new_xyz  = (const float*)d_in[1];   // [4, 2048, 3]
    const float* features = (const float*)d_in[2];   // [4, 64, 8192]
    float* out = (float*)d_out;                      // [4, 67, 2048, 32]

    dim3 tb(32, 8);
    dim3 tg(NPTS / 32, CC / 32 + 1, BB);             // (256, 3, 4)
    transpose_kernel<<<tg, tb>>>(features, xyz);

    qg_kernel<<<(BB * SS) / WPB, 32 * WPB>>>(new_xyz, out);  // 4096 x 64
}

// round 9
// speedup vs baseline: 1.3478x; 1.0072x over previous
#include <cuda_runtime.h>
#include <cuda_bf16.h>

// Problem constants (fixed shapes from setup_inputs)
#define BB      4
#define NPTS    8192
#define SS      2048
#define CC      64
#define NSAMPLE 32
#define R2      0.04f     // 0.2^2
#define OUTCH   (3 + CC)  // 67

#define WPB     2         // warps per block

// Scratch: transposed features [B,N,C] (8MB); xyz+p2 AoS [B,N] float4 (512KB)
__device__ float  g_featT[(size_t)BB * NPTS * CC];
__device__ float4 g_xyzP4[(size_t)BB * NPTS];

// ---------------------------------------------------------------------------
// Kernel 1: transpose features [B,C,N] -> [B,N,C]; last y-slice packs xyz
// into float4 (x, y, z, p2) with p2 computed in the scan's EXACT rounding.
// block (32,8), grid (N/32, C/32 + 1, B).
// ---------------------------------------------------------------------------
__global__ __launch_bounds__(256) void transpose_kernel(
    const float* __restrict__ feat,
    const float* __restrict__ xyz)
{
    const int n0 = blockIdx.x * 32;
    const int b  = blockIdx.z;

    if (blockIdx.y == CC / 32) {
        const int t = threadIdx.y * 32 + threadIdx.x;
        if (t < 32) {
            const int n = n0 + t;
            const float x = __ldg(xyz + ((size_t)b * NPTS + n) * 3 + 0);
            const float y = __ldg(xyz + ((size_t)b * NPTS + n) * 3 + 1);
            const float z = __ldg(xyz + ((size_t)b * NPTS + n) * 3 + 2);
            // p2 bit-identical to the reference's p2 = (x*x + y*y) + z*z
            const float p2 = __fadd_rn(__fadd_rn(__fmul_rn(x, x),
                                                 __fmul_rn(y, y)),
                                       __fmul_rn(z, z));
            g_xyzP4[(size_t)b * NPTS + n] = make_float4(x, y, z, p2);
        }
        return;
    }

    __shared__ float tsm[32][33];
    const int c0 = blockIdx.y * 32;
    const int tx = threadIdx.x, ty = threadIdx.y;

    const float* fb = feat + (size_t)b * CC * NPTS;
#pragma unroll
    for (int i = 0; i < 4; i++)
        tsm[ty + 8 * i][tx] = fb[(size_t)(c0 + ty + 8 * i) * NPTS + (n0 + tx)];
    __syncthreads();
    float* fT = g_featT + (size_t)b * NPTS * CC;
#pragma unroll
    for (int i = 0; i < 4; i++)
        fT[(size_t)(n0 + ty + 8 * i) * CC + (c0 + tx)] = tsm[tx][ty + 8 * i];
}

// ---------------------------------------------------------------------------
// Kernel 2: fused ball query + group. One warp per query, 2 warps/block.
// Scan: float4 (x,y,z,p2) AoS, 128 pts/chunk, software-pipelined prefetch,
// FOUR INDEPENDENT BALLOTS per chunk (no serialized cnt chain).
// Gather: round-6 wavefront-optimal pattern (validated).
// ---------------------------------------------------------------------------
__global__ __launch_bounds__(64) void qg_kernel(
    const float* __restrict__ new_xyz,  // [B, S, 3]
    float* __restrict__ out)            // [B, 67, S, 32]
{
    __shared__ int   sidx[WPB][NSAMPLE];
    __shared__ float sxyz[WPB][NSAMPLE][3];
    __shared__ float tile[WPB][NSAMPLE * 33];

    const int warp = threadIdx.x >> 5;
    const int lane = threadIdx.x & 31;
    const int w    = blockIdx.x * WPB + warp;  // query id in [0, B*S)
    const int b    = w / SS;
    const int s    = w % SS;

    const float* qptr = new_xyz + ((size_t)b * SS + s) * 3;
    const float qx = qptr[0], qy = qptr[1], qz = qptr[2];
    // Reference arithmetic EXACTLY (plain rn ops, no contraction):
    const float q2 = __fadd_rn(__fadd_rn(__fmul_rn(qx, qx), __fmul_rn(qy, qy)),
                               __fmul_rn(qz, qz));

    const float4* xp = g_xyzP4 + (size_t)b * NPTS;
    const unsigned lmask = (1u << lane) - 1u;

    // --- Ball query: pipelined ascending scan, 128 points per chunk --------
    int cnt = 0;
    float4 cur[4];
#pragma unroll
    for (int r = 0; r < 4; r++) cur[r] = __ldg(xp + 32 * r + lane);

    for (int base = 0; base < NPTS; base += 128) {
        // prefetch next chunk before the break decision (hides load latency)
        float4 nxt[4];
        if (base + 128 < NPTS) {
#pragma unroll
            for (int r = 0; r < 4; r++)
                nxt[r] = __ldg(xp + base + 128 + 32 * r + lane);
        }

        // 1) evaluate all four predicates (independent fp chains)
        bool in[4];
#pragma unroll
        for (int r = 0; r < 4; r++) {
            const float4 p = cur[r];
            const float qpd = __fadd_rn(__fadd_rn(__fmul_rn(qx, p.x),
                                                  __fmul_rn(qy, p.y)),
                                        __fmul_rn(qz, p.z));
            const float d2  = __fadd_rn(__fadd_rn(q2, p.w),
                                        __fmul_rn(-2.0f, qpd));
            in[r] = d2 < R2;
        }

        // 2) four independent ballots, issued back-to-back (no cnt chain)
        unsigned m[4];
#pragma unroll
        for (int r = 0; r < 4; r++) m[r] = __ballot_sync(0xffffffffu, in[r]);

        // 3) prefix counts (cheap ALU tree), then rare predicated stores
        int pre[4];
        pre[0] = cnt;
        pre[1] = pre[0] + __popc(m[0]);
        pre[2] = pre[1] + __popc(m[1]);
        pre[3] = pre[2] + __popc(m[2]);
        const int newcnt = pre[3] + __popc(m[3]);

#pragma unroll
        for (int r = 0; r < 4; r++) {
            if (in[r]) {
                const int pos = pre[r] + __popc(m[r] & lmask);
                if (pos < NSAMPLE) {
                    sidx[warp][pos]    = base + 32 * r + lane;
                    sxyz[warp][pos][0] = cur[r].x;
                    sxyz[warp][pos][1] = cur[r].y;
                    sxyz[warp][pos][2] = cur[r].z;
                }
            }
        }
        cnt = newcnt;
        if (cnt >= NSAMPLE) break;             // warp-uniform
#pragma unroll
        for (int r = 0; r < 4; r++) cur[r] = nxt[r];
    }

    // Empty-ball fallback: slot 0 = point 0 (matches reference idx=0)
    if (cnt == 0 && lane == 0) {
        const float4 p0 = __ldg(xp);
        sidx[warp][0]    = 0;
        sxyz[warp][0][0] = p0.x;
        sxyz[warp][0][1] = p0.y;
        sxyz[warp][0][2] = p0.z;
    }
    __syncwarp();

    const int total = (cnt == 0) ? 1 : ((cnt < NSAMPLE) ? cnt : NSAMPLE);
    const int slot  = (lane < total) ? lane : 0;     // pad with first
    const int myidx = sidx[warp][slot];

    // --- grouped_xyz = xyz[idx] - new_xyz (coords captured during scan) ----
    const size_t cs    = (size_t)SS * NSAMPLE;
    const size_t obase = (((size_t)b * OUTCH) * SS + s) * NSAMPLE + lane;
    out[obase + 0 * cs] = sxyz[warp][slot][0] - qx;
    out[obase + 1 * cs] = sxyz[warp][slot][1] - qy;
    out[obase + 2 * cs] = sxyz[warp][slot][2] - qz;

    // --- grouped_features: wavefront-optimal cooperative gather -------------
    const float* fT = g_featT + (size_t)b * NPTS * CC;
    float*       tw = tile[warp];

    const int csub = lane >> 3;       // store: channel sub-id (0..3)
    const int k4   = (lane & 7) * 4;  // store: first of 4 samples

#pragma unroll
    for (int h = 0; h < 2; h++) {     // two 32-channel halves
        // 32 coalesced 128B half-row loads (1 wavefront each), MLP=8
#pragma unroll
        for (int m0 = 0; m0 < NSAMPLE; m0 += 8) {
            float v[8];
#pragma unroll
            for (int mm = 0; mm < 8; mm++) {
                const int im = __shfl_sync(0xffffffffu, myidx, m0 + mm);
                v[mm] = __ldg(fT + (size_t)im * CC + h * 32 + lane);
            }
#pragma unroll
            for (int mm = 0; mm < 8; mm++)
                tw[(m0 + mm) * 33 + lane] = v[mm];
        }
        __syncwarp();
        // 8 STG.128: each instr covers 4 channels x 8 sample-quads.
        // LDS banks: (k4+j)*33 + c == k4+j+c (mod 32) -> conflict-free
#pragma unroll
        for (int cc = 0; cc < 8; cc++) {
            const int c = cc * 4 + csub;          // channel within half
            float4 o;
            o.x = tw[(k4 + 0) * 33 + c];
            o.y = tw[(k4 + 1) * 33 + c];
            o.z = tw[(k4 + 2) * 33 + c];
            o.w = tw[(k4 + 3) * 33 + c];
            float* dst = out + (((size_t)b * OUTCH + 3 + h * 32 + c) * SS + s)
                             * NSAMPLE + k4;
            *(float4*)dst = o;
        }
        __syncwarp();
    }
}

extern "C" void kernel_launch(void* const* d_in, const int* in_sizes, int n_in,
                              void* d_out, int out_size) {
    const float* xyz      = (const float*)d_in[0];   // [4, 8192, 3]
    const float* new_xyz  = (const float*)d_in[1];   // [4, 2048, 3]
    const float* features = (const float*)d_in[2];   // [4, 64, 8192]
    float* out = (float*)d_out;                      // [4, 67, 2048, 32]

    dim3 tb(32, 8);
    dim3 tg(NPTS / 32, CC / 32 + 1, BB);             // (256, 3, 4)
    transpose_kernel<<<tg, tb>>>(features, xyz);

    qg_kernel<<<(BB * SS) / WPB, 32 * WPB>>>(new_xyz, out);  // 4096 x 64
}